// round 2
// baseline (speedup 1.0000x reference)
#include <cuda_runtime.h>

// Problem constants
#define BATCH 4
#define SEQ   2048
#define HEADS 8
#define HDIM  64
#define DMODEL 512
#define MROWS (BATCH * SEQ)   // 8192

// ---------------------------------------------------------------------------
// Device scratch (allocation-free per harness rules)
// ---------------------------------------------------------------------------
__device__ float g_qh[BATCH * HEADS * SEQ * HDIM];    // head-split Q  (16 MB)
__device__ float g_kh[BATCH * HEADS * SEQ * HDIM];    // head-split K  (16 MB)
__device__ float g_vh[BATCH * HEADS * SEQ * HDIM];    // head-split V  (16 MB)
__device__ float g_ctx[MROWS * DMODEL];               // merged-head attn output (16 MB)
// Fallback attn buffer if harness d_out only holds `out` (537 MB bss, not an alloc)
__device__ float g_attn[(size_t)BATCH * HEADS * SEQ * SEQ];

// ---------------------------------------------------------------------------
// Generic NT GEMM with bias: C[m,n] = sum_k X[m,k] * W[n,k] + bias[n]
// X: [M x 512] row-major, W: [512 x 512] row-major.
// Tile 128(M) x 64(N), BK=32, 256 threads, 8x4 microtile.
// mode 0/1/2: write head-split into g_qh/g_kh/g_vh. mode 3: X is g_ctx,
// write plain row-major into OutPlain.
// ---------------------------------------------------------------------------
__global__ void __launch_bounds__(256, 2)
gemm_nt_bias(const float* __restrict__ X,
             const float* __restrict__ W,
             const float* __restrict__ bias,
             float* __restrict__ OutPlain,
             int mode) {
    __shared__ float As[32][128];
    __shared__ float Bs[32][64];

    const float* Xp = (mode == 3) ? g_ctx : X;
    float* Ohs = (mode == 0) ? g_qh : (mode == 1) ? g_kh : g_vh;

    const int m0 = blockIdx.y * 128;
    const int n0 = blockIdx.x * 64;
    const int tid = threadIdx.x;
    const int tx = tid & 15;        // N microtile index (4 cols)
    const int ty = tid >> 4;        // M microtile index (8 rows)

    float acc[8][4] = {};

    for (int k0 = 0; k0 < DMODEL; k0 += 32) {
        // Load A tile: 128 rows x 32 k = 1024 float4 (transposed into As[k][r])
        #pragma unroll
        for (int i = tid; i < 1024; i += 256) {
            const int r  = i & 127;
            const int cq = i >> 7;          // 0..7
            float4 va = *(const float4*)(Xp + (size_t)(m0 + r) * DMODEL + k0 + cq * 4);
            As[cq * 4 + 0][r] = va.x;
            As[cq * 4 + 1][r] = va.y;
            As[cq * 4 + 2][r] = va.z;
            As[cq * 4 + 3][r] = va.w;
        }
        // Load B tile: 64 rows x 32 k = 512 float4 (transposed into Bs[k][r])
        #pragma unroll
        for (int i = tid; i < 512; i += 256) {
            const int r  = i & 63;
            const int cq = i >> 6;
            float4 vb = *(const float4*)(W + (size_t)(n0 + r) * DMODEL + k0 + cq * 4);
            Bs[cq * 4 + 0][r] = vb.x;
            Bs[cq * 4 + 1][r] = vb.y;
            Bs[cq * 4 + 2][r] = vb.z;
            Bs[cq * 4 + 3][r] = vb.w;
        }
        __syncthreads();
        #pragma unroll
        for (int kk = 0; kk < 32; kk++) {
            float4 a0 = *(const float4*)&As[kk][ty * 8];
            float4 a1 = *(const float4*)&As[kk][ty * 8 + 4];
            float4 b  = *(const float4*)&Bs[kk][tx * 4];
            acc[0][0] += a0.x * b.x; acc[0][1] += a0.x * b.y; acc[0][2] += a0.x * b.z; acc[0][3] += a0.x * b.w;
            acc[1][0] += a0.y * b.x; acc[1][1] += a0.y * b.y; acc[1][2] += a0.y * b.z; acc[1][3] += a0.y * b.w;
            acc[2][0] += a0.z * b.x; acc[2][1] += a0.z * b.y; acc[2][2] += a0.z * b.z; acc[2][3] += a0.z * b.w;
            acc[3][0] += a0.w * b.x; acc[3][1] += a0.w * b.y; acc[3][2] += a0.w * b.z; acc[3][3] += a0.w * b.w;
            acc[4][0] += a1.x * b.x; acc[4][1] += a1.x * b.y; acc[4][2] += a1.x * b.z; acc[4][3] += a1.x * b.w;
            acc[5][0] += a1.y * b.x; acc[5][1] += a1.y * b.y; acc[5][2] += a1.y * b.z; acc[5][3] += a1.y * b.w;
            acc[6][0] += a1.z * b.x; acc[6][1] += a1.z * b.y; acc[6][2] += a1.z * b.z; acc[6][3] += a1.z * b.w;
            acc[7][0] += a1.w * b.x; acc[7][1] += a1.w * b.y; acc[7][2] += a1.w * b.z; acc[7][3] += a1.w * b.w;
        }
        __syncthreads();
    }

    const int ncol = n0 + tx * 4;
    float4 bb = *(const float4*)(bias + ncol);

    #pragma unroll
    for (int i = 0; i < 8; i++) {
        const int m = m0 + ty * 8 + i;
        float4 o;
        o.x = acc[i][0] + bb.x;
        o.y = acc[i][1] + bb.y;
        o.z = acc[i][2] + bb.z;
        o.w = acc[i][3] + bb.w;
        if (mode == 3) {
            *(float4*)(OutPlain + (size_t)m * DMODEL + ncol) = o;
        } else {
            const int b  = m >> 11;          // /SEQ
            const int s  = m & (SEQ - 1);
            const int h  = ncol >> 6;        // /HDIM
            const int dh = ncol & 63;        // stays within head (ncol multiple of 4)
            *(float4*)(Ohs + ((((size_t)b * HEADS + h) * SEQ + s) * HDIM + dh)) = o;
        }
    }
}

// ---------------------------------------------------------------------------
// Scores: attn[bh, m, n] = (qh[bh,m,:] . kh[bh,n,:]) * 0.125   (K = 64)
// Tile 128(M) x 64(N), BK=32, 8x4 microtile.
// ---------------------------------------------------------------------------
__global__ void __launch_bounds__(256, 2)
scores_kernel(float* __restrict__ attn_ext) {
    __shared__ float As[32][128];
    __shared__ float Bs[32][64];

    const int bh = blockIdx.z;
    const float* A  = g_qh + (size_t)bh * SEQ * HDIM;
    const float* Bm = g_kh + (size_t)bh * SEQ * HDIM;
    float* C = (attn_ext ? attn_ext : g_attn) + (size_t)bh * SEQ * SEQ;

    const int m0 = blockIdx.y * 128;
    const int n0 = blockIdx.x * 64;
    const int tid = threadIdx.x;
    const int tx = tid & 15;
    const int ty = tid >> 4;

    float acc[8][4] = {};

    for (int k0 = 0; k0 < HDIM; k0 += 32) {
        #pragma unroll
        for (int i = tid; i < 1024; i += 256) {
            const int r  = i & 127;
            const int cq = i >> 7;
            float4 va = *(const float4*)(A + (size_t)(m0 + r) * HDIM + k0 + cq * 4);
            As[cq * 4 + 0][r] = va.x;
            As[cq * 4 + 1][r] = va.y;
            As[cq * 4 + 2][r] = va.z;
            As[cq * 4 + 3][r] = va.w;
        }
        #pragma unroll
        for (int i = tid; i < 512; i += 256) {
            const int r  = i & 63;
            const int cq = i >> 6;
            float4 vb = *(const float4*)(Bm + (size_t)(n0 + r) * HDIM + k0 + cq * 4);
            Bs[cq * 4 + 0][r] = vb.x;
            Bs[cq * 4 + 1][r] = vb.y;
            Bs[cq * 4 + 2][r] = vb.z;
            Bs[cq * 4 + 3][r] = vb.w;
        }
        __syncthreads();
        #pragma unroll
        for (int kk = 0; kk < 32; kk++) {
            float4 a0 = *(const float4*)&As[kk][ty * 8];
            float4 a1 = *(const float4*)&As[kk][ty * 8 + 4];
            float4 b  = *(const float4*)&Bs[kk][tx * 4];
            acc[0][0] += a0.x * b.x; acc[0][1] += a0.x * b.y; acc[0][2] += a0.x * b.z; acc[0][3] += a0.x * b.w;
            acc[1][0] += a0.y * b.x; acc[1][1] += a0.y * b.y; acc[1][2] += a0.y * b.z; acc[1][3] += a0.y * b.w;
            acc[2][0] += a0.z * b.x; acc[2][1] += a0.z * b.y; acc[2][2] += a0.z * b.z; acc[2][3] += a0.z * b.w;
            acc[3][0] += a0.w * b.x; acc[3][1] += a0.w * b.y; acc[3][2] += a0.w * b.z; acc[3][3] += a0.w * b.w;
            acc[4][0] += a1.x * b.x; acc[4][1] += a1.x * b.y; acc[4][2] += a1.x * b.z; acc[4][3] += a1.x * b.w;
            acc[5][0] += a1.y * b.x; acc[5][1] += a1.y * b.y; acc[5][2] += a1.y * b.z; acc[5][3] += a1.y * b.w;
            acc[6][0] += a1.z * b.x; acc[6][1] += a1.z * b.y; acc[6][2] += a1.z * b.z; acc[6][3] += a1.z * b.w;
            acc[7][0] += a1.w * b.x; acc[7][1] += a1.w * b.y; acc[7][2] += a1.w * b.z; acc[7][3] += a1.w * b.w;
        }
        __syncthreads();
    }

    const float scale = 0.125f;  // 1/sqrt(64)
    const int ncol = n0 + tx * 4;
    #pragma unroll
    for (int i = 0; i < 8; i++) {
        const int m = m0 + ty * 8 + i;
        float4 o;
        o.x = acc[i][0] * scale;
        o.y = acc[i][1] * scale;
        o.z = acc[i][2] * scale;
        o.w = acc[i][3] * scale;
        *(float4*)(C + (size_t)m * SEQ + ncol) = o;
    }
}

// ---------------------------------------------------------------------------
// Row softmax over last dim (2048), in place. One block (256 thr) per row.
// ---------------------------------------------------------------------------
__global__ void softmax_kernel(float* __restrict__ attn_ext) {
    float* base = attn_ext ? attn_ext : g_attn;
    float* p = base + (size_t)blockIdx.x * SEQ;
    const int tid = threadIdx.x;

    float4 v0 = *(const float4*)(p + tid * 4);
    float4 v1 = *(const float4*)(p + 1024 + tid * 4);

    float mx = fmaxf(fmaxf(fmaxf(v0.x, v0.y), fmaxf(v0.z, v0.w)),
                     fmaxf(fmaxf(v1.x, v1.y), fmaxf(v1.z, v1.w)));

    __shared__ float red[8];
    #pragma unroll
    for (int o = 16; o > 0; o >>= 1) mx = fmaxf(mx, __shfl_xor_sync(0xffffffffu, mx, o));
    if ((tid & 31) == 0) red[tid >> 5] = mx;
    __syncthreads();
    float bm = red[0];
    #pragma unroll
    for (int i = 1; i < 8; i++) bm = fmaxf(bm, red[i]);
    __syncthreads();

    float e[8];
    e[0] = __expf(v0.x - bm); e[1] = __expf(v0.y - bm);
    e[2] = __expf(v0.z - bm); e[3] = __expf(v0.w - bm);
    e[4] = __expf(v1.x - bm); e[5] = __expf(v1.y - bm);
    e[6] = __expf(v1.z - bm); e[7] = __expf(v1.w - bm);
    float s = e[0] + e[1] + e[2] + e[3] + e[4] + e[5] + e[6] + e[7];

    #pragma unroll
    for (int o = 16; o > 0; o >>= 1) s += __shfl_xor_sync(0xffffffffu, s, o);
    if ((tid & 31) == 0) red[tid >> 5] = s;
    __syncthreads();
    float bs = red[0];
    #pragma unroll
    for (int i = 1; i < 8; i++) bs += red[i];

    const float inv = 1.0f / bs;
    float4 w0, w1;
    w0.x = e[0] * inv; w0.y = e[1] * inv; w0.z = e[2] * inv; w0.w = e[3] * inv;
    w1.x = e[4] * inv; w1.y = e[5] * inv; w1.z = e[6] * inv; w1.w = e[7] * inv;
    *(float4*)(p + tid * 4) = w0;
    *(float4*)(p + 1024 + tid * 4) = w1;
}

// ---------------------------------------------------------------------------
// attn @ V : ctx[b, s, h*64+dh] = sum_k attn[bh, s, k] * vh[bh, k, dh]
// NN GEMM per (b,h): M=2048, N=64, K=2048. Tile 128x64, BK=32, 8x4 microtile.
// ---------------------------------------------------------------------------
__global__ void __launch_bounds__(256, 2)
av_kernel(const float* __restrict__ attn_ext) {
    __shared__ float As[32][128];
    __shared__ float Bs[32][64];

    const int bh = blockIdx.z;
    const float* A  = (attn_ext ? attn_ext : g_attn) + (size_t)bh * SEQ * SEQ;
    const float* Bm = g_vh + (size_t)bh * SEQ * HDIM;
    const int b = bh >> 3;
    const int h = bh & 7;

    const int m0 = blockIdx.y * 128;
    const int tid = threadIdx.x;
    const int tx = tid & 15;
    const int ty = tid >> 4;

    float acc[8][4] = {};

    for (int k0 = 0; k0 < SEQ; k0 += 32) {
        // A tile: attn rows m0..m0+127, cols k0..k0+31 (stride SEQ), transpose in
        #pragma unroll
        for (int i = tid; i < 1024; i += 256) {
            const int r  = i & 127;
            const int cq = i >> 7;
            float4 va = *(const float4*)(A + (size_t)(m0 + r) * SEQ + k0 + cq * 4);
            As[cq * 4 + 0][r] = va.x;
            As[cq * 4 + 1][r] = va.y;
            As[cq * 4 + 2][r] = va.z;
            As[cq * 4 + 3][r] = va.w;
        }
        // B tile: V rows k0..k0+31 (32 x 64, stride 64), direct copy
        #pragma unroll
        for (int i = tid; i < 512; i += 256) {
            const int rr = i >> 4;          // 0..31
            const int cc = (i & 15) * 4;    // 0..60
            *(float4*)&Bs[rr][cc] = *(const float4*)(Bm + (size_t)(k0 + rr) * HDIM + cc);
        }
        __syncthreads();
        #pragma unroll
        for (int kk = 0; kk < 32; kk++) {
            float4 a0 = *(const float4*)&As[kk][ty * 8];
            float4 a1 = *(const float4*)&As[kk][ty * 8 + 4];
            float4 b  = *(const float4*)&Bs[kk][tx * 4];
            acc[0][0] += a0.x * b.x; acc[0][1] += a0.x * b.y; acc[0][2] += a0.x * b.z; acc[0][3] += a0.x * b.w;
            acc[1][0] += a0.y * b.x; acc[1][1] += a0.y * b.y; acc[1][2] += a0.y * b.z; acc[1][3] += a0.y * b.w;
            acc[2][0] += a0.z * b.x; acc[2][1] += a0.z * b.y; acc[2][2] += a0.z * b.z; acc[2][3] += a0.z * b.w;
            acc[3][0] += a0.w * b.x; acc[3][1] += a0.w * b.y; acc[3][2] += a0.w * b.z; acc[3][3] += a0.w * b.w;
            acc[4][0] += a1.x * b.x; acc[4][1] += a1.x * b.y; acc[4][2] += a1.x * b.z; acc[4][3] += a1.x * b.w;
            acc[5][0] += a1.y * b.x; acc[5][1] += a1.y * b.y; acc[5][2] += a1.y * b.z; acc[5][3] += a1.y * b.w;
            acc[6][0] += a1.z * b.x; acc[6][1] += a1.z * b.y; acc[6][2] += a1.z * b.z; acc[6][3] += a1.z * b.w;
            acc[7][0] += a1.w * b.x; acc[7][1] += a1.w * b.y; acc[7][2] += a1.w * b.z; acc[7][3] += a1.w * b.w;
        }
        __syncthreads();
    }

    const int dh = tx * 4;
    #pragma unroll
    for (int i = 0; i < 8; i++) {
        const int s = m0 + ty * 8 + i;
        float4 o;
        o.x = acc[i][0]; o.y = acc[i][1]; o.z = acc[i][2]; o.w = acc[i][3];
        *(float4*)(g_ctx + ((size_t)b * SEQ + s) * DMODEL + h * HDIM + dh) = o;
    }
}

// ---------------------------------------------------------------------------
// Launch
// ---------------------------------------------------------------------------
extern "C" void kernel_launch(void* const* d_in, const int* in_sizes, int n_in,
                              void* d_out, int out_size) {
    const float* q   = (const float*)d_in[0];
    const float* k   = (const float*)d_in[1];
    const float* v   = (const float*)d_in[2];
    const float* w_q = (const float*)d_in[3];
    const float* b_q = (const float*)d_in[4];
    const float* w_k = (const float*)d_in[5];
    const float* b_k = (const float*)d_in[6];
    const float* w_v = (const float*)d_in[7];
    const float* b_v = (const float*)d_in[8];
    const float* w_o = (const float*)d_in[9];
    const float* b_o = (const float*)d_in[10];

    float* out = (float*)d_out;

    const long long OUT_ELEMS  = (long long)BATCH * SEQ * DMODEL;                 // 4,194,304
    const long long ATTN_ELEMS = (long long)BATCH * HEADS * SEQ * (long long)SEQ; // 134,217,728

    // If the harness output buffer covers (out, attn) concatenated, write attn
    // there; otherwise fall back to device scratch.
    float* attn_ptr = ((long long)out_size >= OUT_ELEMS + ATTN_ELEMS)
                          ? (out + OUT_ELEMS)
                          : nullptr;  // kernels fall back to g_attn

    dim3 blk(256);

    // QKV projections (head-split outputs)
    dim3 gproj(DMODEL / 64, MROWS / 128);         // (8, 64)
    gemm_nt_bias<<<gproj, blk>>>(q, w_q, b_q, nullptr, 0);
    gemm_nt_bias<<<gproj, blk>>>(k, w_k, b_k, nullptr, 1);
    gemm_nt_bias<<<gproj, blk>>>(v, w_v, b_v, nullptr, 2);

    // Scores = Q Kᵀ / 8
    dim3 gsc(SEQ / 64, SEQ / 128, BATCH * HEADS); // (32, 16, 32)
    scores_kernel<<<gsc, blk>>>(attn_ptr);

    // Softmax over keys
    softmax_kernel<<<BATCH * HEADS * SEQ, blk>>>(attn_ptr);

    // attn @ V -> merged-head ctx
    dim3 gav(1, SEQ / 128, BATCH * HEADS);        // (1, 16, 32)
    av_kernel<<<gav, blk>>>(attn_ptr);

    // Output projection
    gemm_nt_bias<<<gproj, blk>>>(nullptr, w_o, b_o, out, 3);
}

// round 3
// speedup vs baseline: 1.0716x; 1.0716x over previous
#include <cuda_runtime.h>

// Problem constants
#define BATCH 4
#define SEQ   2048
#define HEADS 8
#define HDIM  64
#define DMODEL 512
#define MROWS (BATCH * SEQ)   // 8192

// ---------------------------------------------------------------------------
// Device scratch (allocation-free per harness rules)
// ---------------------------------------------------------------------------
__device__ float g_qh[BATCH * HEADS * SEQ * HDIM];    // head-split Q  (16 MB)
__device__ float g_kh[BATCH * HEADS * SEQ * HDIM];    // head-split K  (16 MB)
__device__ float g_vh[BATCH * HEADS * SEQ * HDIM];    // head-split V  (16 MB)
__device__ float g_ctx[MROWS * DMODEL];               // merged-head attn output (16 MB)
// Fallback attn buffer if harness d_out only holds `out` (537 MB bss, not an alloc)
__device__ float g_attn[(size_t)BATCH * HEADS * SEQ * SEQ];

// ---------------------------------------------------------------------------
// Generic NT GEMM with bias: C[m,n] = sum_k X[m,k] * W[n,k] + bias[n]
// X: [M x 512] row-major, W: [512 x 512] row-major.
// Tile 128(M) x 128(N), BK=32, 256 threads, 8x8 microtile.
// mode 0/1/2: write head-split into g_qh/g_kh/g_vh. mode 3: X is g_ctx,
// write plain row-major into OutPlain.
// ---------------------------------------------------------------------------
__global__ void __launch_bounds__(256, 2)
gemm_nt_bias(const float* __restrict__ X,
             const float* __restrict__ W,
             const float* __restrict__ bias,
             float* __restrict__ OutPlain,
             int mode) {
    __shared__ float As[32][128];
    __shared__ float Bs[32][128];

    const float* Xp = (mode == 3) ? g_ctx : X;
    float* Ohs = (mode == 0) ? g_qh : (mode == 1) ? g_kh : g_vh;

    const int m0 = blockIdx.y * 128;
    const int n0 = blockIdx.x * 128;
    const int tid = threadIdx.x;
    const int tx = tid & 15;        // N microtile index (8 cols)
    const int ty = tid >> 4;        // M microtile index (8 rows)

    float acc[8][8] = {};

    for (int k0 = 0; k0 < DMODEL; k0 += 32) {
        // A tile: 128 rows x 32 k = 1024 float4, transposed into As[k][m]
        #pragma unroll
        for (int i = tid; i < 1024; i += 256) {
            const int r  = i & 127;
            const int cq = i >> 7;          // 0..7
            float4 va = *(const float4*)(Xp + (size_t)(m0 + r) * DMODEL + k0 + cq * 4);
            As[cq * 4 + 0][r] = va.x;
            As[cq * 4 + 1][r] = va.y;
            As[cq * 4 + 2][r] = va.z;
            As[cq * 4 + 3][r] = va.w;
        }
        // B tile: 128 rows x 32 k = 1024 float4, transposed into Bs[k][n]
        #pragma unroll
        for (int i = tid; i < 1024; i += 256) {
            const int r  = i & 127;
            const int cq = i >> 7;
            float4 vb = *(const float4*)(W + (size_t)(n0 + r) * DMODEL + k0 + cq * 4);
            Bs[cq * 4 + 0][r] = vb.x;
            Bs[cq * 4 + 1][r] = vb.y;
            Bs[cq * 4 + 2][r] = vb.z;
            Bs[cq * 4 + 3][r] = vb.w;
        }
        __syncthreads();
        #pragma unroll
        for (int kk = 0; kk < 32; kk++) {
            float a[8], b[8];
            *(float4*)&a[0] = *(const float4*)&As[kk][ty * 8];
            *(float4*)&a[4] = *(const float4*)&As[kk][ty * 8 + 4];
            *(float4*)&b[0] = *(const float4*)&Bs[kk][tx * 8];
            *(float4*)&b[4] = *(const float4*)&Bs[kk][tx * 8 + 4];
            #pragma unroll
            for (int i = 0; i < 8; i++)
                #pragma unroll
                for (int j = 0; j < 8; j++)
                    acc[i][j] += a[i] * b[j];
        }
        __syncthreads();
    }

    const int ncol = n0 + tx * 8;
    float bb[8];
    *(float4*)&bb[0] = *(const float4*)(bias + ncol);
    *(float4*)&bb[4] = *(const float4*)(bias + ncol + 4);

    #pragma unroll
    for (int i = 0; i < 8; i++) {
        const int m = m0 + ty * 8 + i;
        float o[8];
        #pragma unroll
        for (int j = 0; j < 8; j++) o[j] = acc[i][j] + bb[j];
        if (mode == 3) {
            *(float4*)(OutPlain + (size_t)m * DMODEL + ncol)     = *(float4*)&o[0];
            *(float4*)(OutPlain + (size_t)m * DMODEL + ncol + 4) = *(float4*)&o[4];
        } else {
            const int b  = m >> 11;          // /SEQ
            const int s  = m & (SEQ - 1);
            const int h  = ncol >> 6;        // /HDIM (ncol multiple of 8: stays in head)
            const int dh = ncol & 63;
            float* dst = Ohs + ((((size_t)b * HEADS + h) * SEQ + s) * HDIM + dh);
            *(float4*)(dst)     = *(float4*)&o[0];
            *(float4*)(dst + 4) = *(float4*)&o[4];
        }
    }
}

// ---------------------------------------------------------------------------
// Scores: attn[bh, m, n] = (qh[bh,m,:] . kh[bh,n,:]) * 0.125   (K = 64)
// Tile 128(M) x 128(N), BK=32, 8x8 microtile.
// ---------------------------------------------------------------------------
__global__ void __launch_bounds__(256, 2)
scores_kernel(float* __restrict__ attn_ext) {
    __shared__ float As[32][128];
    __shared__ float Bs[32][128];

    const int bh = blockIdx.z;
    const float* A  = g_qh + (size_t)bh * SEQ * HDIM;
    const float* Bm = g_kh + (size_t)bh * SEQ * HDIM;
    float* C = (attn_ext ? attn_ext : g_attn) + (size_t)bh * SEQ * SEQ;

    const int m0 = blockIdx.y * 128;
    const int n0 = blockIdx.x * 128;
    const int tid = threadIdx.x;
    const int tx = tid & 15;
    const int ty = tid >> 4;

    float acc[8][8] = {};

    for (int k0 = 0; k0 < HDIM; k0 += 32) {
        #pragma unroll
        for (int i = tid; i < 1024; i += 256) {
            const int r  = i & 127;
            const int cq = i >> 7;
            float4 va = *(const float4*)(A + (size_t)(m0 + r) * HDIM + k0 + cq * 4);
            As[cq * 4 + 0][r] = va.x;
            As[cq * 4 + 1][r] = va.y;
            As[cq * 4 + 2][r] = va.z;
            As[cq * 4 + 3][r] = va.w;
        }
        #pragma unroll
        for (int i = tid; i < 1024; i += 256) {
            const int r  = i & 127;
            const int cq = i >> 7;
            float4 vb = *(const float4*)(Bm + (size_t)(n0 + r) * HDIM + k0 + cq * 4);
            Bs[cq * 4 + 0][r] = vb.x;
            Bs[cq * 4 + 1][r] = vb.y;
            Bs[cq * 4 + 2][r] = vb.z;
            Bs[cq * 4 + 3][r] = vb.w;
        }
        __syncthreads();
        #pragma unroll
        for (int kk = 0; kk < 32; kk++) {
            float a[8], b[8];
            *(float4*)&a[0] = *(const float4*)&As[kk][ty * 8];
            *(float4*)&a[4] = *(const float4*)&As[kk][ty * 8 + 4];
            *(float4*)&b[0] = *(const float4*)&Bs[kk][tx * 8];
            *(float4*)&b[4] = *(const float4*)&Bs[kk][tx * 8 + 4];
            #pragma unroll
            for (int i = 0; i < 8; i++)
                #pragma unroll
                for (int j = 0; j < 8; j++)
                    acc[i][j] += a[i] * b[j];
        }
        __syncthreads();
    }

    const float scale = 0.125f;  // 1/sqrt(64)
    const int ncol = n0 + tx * 8;
    #pragma unroll
    for (int i = 0; i < 8; i++) {
        const int m = m0 + ty * 8 + i;
        float o[8];
        #pragma unroll
        for (int j = 0; j < 8; j++) o[j] = acc[i][j] * scale;
        *(float4*)(C + (size_t)m * SEQ + ncol)     = *(float4*)&o[0];
        *(float4*)(C + (size_t)m * SEQ + ncol + 4) = *(float4*)&o[4];
    }
}

// ---------------------------------------------------------------------------
// Row softmax over last dim (2048), in place. One block (256 thr) per row.
// ---------------------------------------------------------------------------
__global__ void softmax_kernel(float* __restrict__ attn_ext) {
    float* base = attn_ext ? attn_ext : g_attn;
    float* p = base + (size_t)blockIdx.x * SEQ;
    const int tid = threadIdx.x;

    float4 v0 = *(const float4*)(p + tid * 4);
    float4 v1 = *(const float4*)(p + 1024 + tid * 4);

    float mx = fmaxf(fmaxf(fmaxf(v0.x, v0.y), fmaxf(v0.z, v0.w)),
                     fmaxf(fmaxf(v1.x, v1.y), fmaxf(v1.z, v1.w)));

    __shared__ float red[8];
    #pragma unroll
    for (int o = 16; o > 0; o >>= 1) mx = fmaxf(mx, __shfl_xor_sync(0xffffffffu, mx, o));
    if ((tid & 31) == 0) red[tid >> 5] = mx;
    __syncthreads();
    float bm = red[0];
    #pragma unroll
    for (int i = 1; i < 8; i++) bm = fmaxf(bm, red[i]);
    __syncthreads();

    float e[8];
    e[0] = __expf(v0.x - bm); e[1] = __expf(v0.y - bm);
    e[2] = __expf(v0.z - bm); e[3] = __expf(v0.w - bm);
    e[4] = __expf(v1.x - bm); e[5] = __expf(v1.y - bm);
    e[6] = __expf(v1.z - bm); e[7] = __expf(v1.w - bm);
    float s = e[0] + e[1] + e[2] + e[3] + e[4] + e[5] + e[6] + e[7];

    #pragma unroll
    for (int o = 16; o > 0; o >>= 1) s += __shfl_xor_sync(0xffffffffu, s, o);
    if ((tid & 31) == 0) red[tid >> 5] = s;
    __syncthreads();
    float bs = red[0];
    #pragma unroll
    for (int i = 1; i < 8; i++) bs += red[i];

    const float inv = 1.0f / bs;
    float4 w0, w1;
    w0.x = e[0] * inv; w0.y = e[1] * inv; w0.z = e[2] * inv; w0.w = e[3] * inv;
    w1.x = e[4] * inv; w1.y = e[5] * inv; w1.z = e[6] * inv; w1.w = e[7] * inv;
    *(float4*)(p + tid * 4) = w0;
    *(float4*)(p + 1024 + tid * 4) = w1;
}

// ---------------------------------------------------------------------------
// attn @ V : ctx[b, s, h*64+dh] = sum_k attn[bh, s, k] * vh[bh, k, dh]
// NN GEMM per (b,h): M=2048, N=64, K=2048.
// Tile 256(M) x 64(N), BK=32, 256 threads, 8x8 microtile (tx 0..7, ty 0..31).
// ---------------------------------------------------------------------------
__global__ void __launch_bounds__(256, 2)
av_kernel(const float* __restrict__ attn_ext) {
    __shared__ float As[32][256];
    __shared__ float Bs[32][64];

    const int bh = blockIdx.z;
    const float* A  = (attn_ext ? attn_ext : g_attn) + (size_t)bh * SEQ * SEQ;
    const float* Bm = g_vh + (size_t)bh * SEQ * HDIM;
    const int b = bh >> 3;
    const int h = bh & 7;

    const int m0 = blockIdx.y * 256;
    const int tid = threadIdx.x;
    const int tx = tid & 7;         // N microtile (8 cols of 64)
    const int ty = tid >> 3;        // M microtile (8 rows of 256)

    float acc[8][8] = {};

    for (int k0 = 0; k0 < SEQ; k0 += 32) {
        // A tile: attn rows m0..m0+255, cols k0..k0+31 (stride SEQ): 2048 float4
        #pragma unroll
        for (int i = tid; i < 2048; i += 256) {
            const int r  = i & 255;
            const int cq = i >> 8;          // 0..7
            float4 va = *(const float4*)(A + (size_t)(m0 + r) * SEQ + k0 + cq * 4);
            As[cq * 4 + 0][r] = va.x;
            As[cq * 4 + 1][r] = va.y;
            As[cq * 4 + 2][r] = va.z;
            As[cq * 4 + 3][r] = va.w;
        }
        // B tile: V rows k0..k0+31 (32 x 64, stride 64), direct copy: 512 float4
        #pragma unroll
        for (int i = tid; i < 512; i += 256) {
            const int rr = i >> 4;          // 0..31
            const int cc = (i & 15) * 4;    // 0..60
            *(float4*)&Bs[rr][cc] = *(const float4*)(Bm + (size_t)(k0 + rr) * HDIM + cc);
        }
        __syncthreads();
        #pragma unroll
        for (int kk = 0; kk < 32; kk++) {
            float a[8], bv[8];
            *(float4*)&a[0]  = *(const float4*)&As[kk][ty * 8];
            *(float4*)&a[4]  = *(const float4*)&As[kk][ty * 8 + 4];
            *(float4*)&bv[0] = *(const float4*)&Bs[kk][tx * 8];
            *(float4*)&bv[4] = *(const float4*)&Bs[kk][tx * 8 + 4];
            #pragma unroll
            for (int i = 0; i < 8; i++)
                #pragma unroll
                for (int j = 0; j < 8; j++)
                    acc[i][j] += a[i] * bv[j];
        }
        __syncthreads();
    }

    const int dh = tx * 8;
    #pragma unroll
    for (int i = 0; i < 8; i++) {
        const int s = m0 + ty * 8 + i;
        float* dst = g_ctx + ((size_t)b * SEQ + s) * DMODEL + h * HDIM + dh;
        *(float4*)(dst)     = *(float4*)&acc[i][0];
        *(float4*)(dst + 4) = *(float4*)&acc[i][4];
    }
}

// ---------------------------------------------------------------------------
// Launch
// ---------------------------------------------------------------------------
extern "C" void kernel_launch(void* const* d_in, const int* in_sizes, int n_in,
                              void* d_out, int out_size) {
    const float* q   = (const float*)d_in[0];
    const float* k   = (const float*)d_in[1];
    const float* v   = (const float*)d_in[2];
    const float* w_q = (const float*)d_in[3];
    const float* b_q = (const float*)d_in[4];
    const float* w_k = (const float*)d_in[5];
    const float* b_k = (const float*)d_in[6];
    const float* w_v = (const float*)d_in[7];
    const float* b_v = (const float*)d_in[8];
    const float* w_o = (const float*)d_in[9];
    const float* b_o = (const float*)d_in[10];

    float* out = (float*)d_out;

    const long long OUT_ELEMS  = (long long)BATCH * SEQ * DMODEL;                 // 4,194,304
    const long long ATTN_ELEMS = (long long)BATCH * HEADS * SEQ * (long long)SEQ; // 134,217,728

    // If the harness output buffer covers (out, attn) concatenated, write attn
    // there; otherwise fall back to device scratch.
    float* attn_ptr = ((long long)out_size >= OUT_ELEMS + ATTN_ELEMS)
                          ? (out + OUT_ELEMS)
                          : nullptr;  // kernels fall back to g_attn

    dim3 blk(256);

    // QKV projections (head-split outputs)
    dim3 gproj(DMODEL / 128, MROWS / 128);        // (4, 64)
    gemm_nt_bias<<<gproj, blk>>>(q, w_q, b_q, nullptr, 0);
    gemm_nt_bias<<<gproj, blk>>>(k, w_k, b_k, nullptr, 1);
    gemm_nt_bias<<<gproj, blk>>>(v, w_v, b_v, nullptr, 2);

    // Scores = Q Kᵀ / 8
    dim3 gsc(SEQ / 128, SEQ / 128, BATCH * HEADS); // (16, 16, 32)
    scores_kernel<<<gsc, blk>>>(attn_ptr);

    // Softmax over keys
    softmax_kernel<<<BATCH * HEADS * SEQ, blk>>>(attn_ptr);

    // attn @ V -> merged-head ctx
    dim3 gav(1, SEQ / 256, BATCH * HEADS);         // (1, 8, 32)
    av_kernel<<<gav, blk>>>(attn_ptr);

    // Output projection
    gemm_nt_bias<<<gproj, blk>>>(nullptr, w_o, b_o, out, 3);
}